// round 17
// baseline (speedup 1.0000x reference)
#include <cuda_runtime.h>

#define DD 128
#define KK 8
#define CC 2000
#define UU 20000
#define NN_MAX 50000
#define QB 296                 // blocks in k_q (2 per SM on 148 SMs)
#define CK (CC * KK)           // 16000
#define UASB 79                // k_ua_sum blocks = ceil(20000/256)

typedef unsigned long long ull;

// ---- scratch (device globals; no allocation allowed) ----
__device__ float g_Wc[CC * KK * DD];     // softmax(CA) TRANSPOSED: [c][k][d]
__device__ float g_A[NN_MAX * KK];       // pooled activity features
__device__ float g_csum_part[UASB * KK]; // per-block colsum(exp(UA)) partials
__device__ float g_Qpart[QB * CK];       // per-block Q partials
__device__ float g_Qs[CK];               // (1 - slide - guess) * Q / csum
__device__ float g_gb[CC];               // guess bias

// ---- f32x2 packed helpers (FFMA2 only reachable via PTX) ----
__device__ __forceinline__ ull pack2(float lo, float hi) {
    ull r;
    asm("mov.b64 %0, {%1, %2};" : "=l"(r) : "f"(lo), "f"(hi));
    return r;
}
__device__ __forceinline__ ull fma2(ull a, ull b, ull c) {
    ull d;
    asm("fma.rn.f32x2 %0, %1, %2, %3;" : "=l"(d) : "l"(a), "l"(b), "l"(c));
    return d;
}
__device__ __forceinline__ ull mul2(ull a, ull b) {
    ull d;
    asm("mul.rn.f32x2 %0, %1, %2;" : "=l"(d) : "l"(a), "l"(b));
    return d;
}

// ---- 1: per-block colsum of exp(UA) partials (no init, no atomics) ----
__global__ void k_ua_sum(const float* __restrict__ UA) {
    __shared__ float sm[8 * KK];
    int t = threadIdx.x, lane = t & 31, wid = t >> 5;
    int u = blockIdx.x * blockDim.x + t;
    float ps[KK];
#pragma unroll
    for (int k = 0; k < KK; k++)
        ps[k] = (u < UU) ? __expf(UA[u * KK + k]) : 0.f;
#pragma unroll
    for (int o = 16; o; o >>= 1)
#pragma unroll
        for (int k = 0; k < KK; k++)
            ps[k] += __shfl_xor_sync(0xffffffffu, ps[k], o);
    if (lane == 0)
#pragma unroll
        for (int k = 0; k < KK; k++) sm[wid * KK + k] = ps[k];
    __syncthreads();
    if (t < KK) {
        float s = sm[t];
#pragma unroll
        for (int w = 1; w < 8; w++) s += sm[w * KK + t];
        g_csum_part[blockIdx.x * KK + t] = s;
    }
}

// ---- 2: Wc = softmax(CA, axis=D), stored TRANSPOSED [c][k][d]. ----
__global__ void k_wc(const float* __restrict__ CA) {
    __shared__ float s[DD * 9];   // 4.5KB, row stride 9 (conflict-free columns)
    int c = blockIdx.x, t = threadIdx.x;  // 256 threads
    const float4* src = (const float4*)(CA + (size_t)c * DD * KK);
    float4 v = src[t];
    int base = t * 4;             // base%8 is 0 or 4 -> all 4 in same row d
    int d0 = base >> 3, k0 = base & 7;
    float* sp = s + d0 * 9 + k0;
    sp[0] = v.x; sp[1] = v.y; sp[2] = v.z; sp[3] = v.w;
    __syncthreads();
    int w = t >> 5, lane = t & 31;  // warp w owns behavior column k=w
    float e[4], sum = 0.f;
#pragma unroll
    for (int j = 0; j < 4; j++) {
        int d = lane + 32 * j;
        e[j] = __expf(s[d * 9 + w]);
        sum += e[j];
    }
#pragma unroll
    for (int o = 16; o; o >>= 1) sum += __shfl_xor_sync(0xffffffffu, sum, o);
    float inv = __fdividef(1.f, sum);
    float* dst = g_Wc + (size_t)c * KK * DD + w * DD;  // [c][k=w][.]
#pragma unroll
    for (int j = 0; j < 4; j++)
        dst[lane + 32 * j] = e[j] * inv;   // coalesced 128B per warp-store
}

// ---- 3: A[i,k] = sum_d X[i,d] * WcT[cour[i],k,d] : warp per TWO samples. ----
__global__ void k_a(const float* __restrict__ X, const int* __restrict__ cour, int n) {
    int w = blockIdx.x * (blockDim.x >> 5) + (threadIdx.x >> 5);
    int lane = threadIdx.x & 31;
    int i0 = w * 2;
    if (i0 >= n) return;
    bool two = (i0 + 1 < n);
    int i1 = two ? i0 + 1 : i0;
    int ca = __ldg(cour + i0), cb = __ldg(cour + i1);
    float4 x0 = ((const float4*)(X + (size_t)i0 * DD))[lane];  // d = 4*lane..+3
    float4 x1 = ((const float4*)(X + (size_t)i1 * DD))[lane];
    const float* wa = g_Wc + (size_t)ca * KK * DD;
    const float* wb = g_Wc + (size_t)cb * KK * DD;
    float A0[KK], A1[KK];
#pragma unroll
    for (int k = 0; k < KK; k++) {
        float4 va = ((const float4*)(wa + k * DD))[lane];
        float4 vb = ((const float4*)(wb + k * DD))[lane];
        A0[k] = fmaf(x0.x, va.x, fmaf(x0.y, va.y, fmaf(x0.z, va.z, x0.w * va.w)));
        A1[k] = fmaf(x1.x, vb.x, fmaf(x1.y, vb.y, fmaf(x1.z, vb.z, x1.w * vb.w)));
    }
#pragma unroll
    for (int o = 16; o; o >>= 1)
#pragma unroll
        for (int k = 0; k < KK; k++) {
            A0[k] += __shfl_xor_sync(0xffffffffu, A0[k], o);
            A1[k] += __shfl_xor_sync(0xffffffffu, A1[k], o);
        }
    if (lane == 0) {
        float4* ar = (float4*)(g_A + (size_t)i0 * KK);
        ar[0] = make_float4(A0[0], A0[1], A0[2], A0[3]);
        ar[1] = make_float4(A0[4], A0[5], A0[6], A0[7]);
        if (two) {
            float4* br = (float4*)(g_A + (size_t)i1 * KK);
            br[0] = make_float4(A1[0], A1[1], A1[2], A1[3]);
            br[1] = make_float4(A1[4], A1[5], A1[6], A1[7]);
        }
    }
}

// ---- 4: Q partials. TWO rows per barrier (measured 48us; unchanged). ----
__global__ void __launch_bounds__(256, 2) k_q(const float* __restrict__ UC,
                                              const float* __restrict__ UA, int rpb) {
    __shared__ float red[2][2][8];
    __shared__ __align__(8) float sua[2][2][8];
    int t = threadIdx.x, lane = t & 31, wid = t >> 5;
    int c0 = t * 8;
    bool act = (c0 < CC);
    ull q[32];  // q[j*4+p] = (Q[c0+j][2p], Q[c0+j][2p+1]) partial
#pragma unroll
    for (int j = 0; j < 32; j++) q[j] = 0ull;

    int u0 = blockIdx.x * rpb;
    int u1 = u0 + rpb; if (u1 > UU) u1 = UU;
    int nrows = u1 - u0;
    int npairs = nrows >> 1;

    float4 pa0, pa1, pb0, pb1;
    pa0 = pa1 = pb0 = pb1 = make_float4(0, 0, 0, 0);
    if (act && npairs > 0) {
        const float* r0 = UC + (size_t)u0 * CC + c0;
        pa0 = *(const float4*)r0;        pa1 = *(const float4*)(r0 + 4);
        pb0 = *(const float4*)(r0 + CC); pb1 = *(const float4*)(r0 + CC + 4);
    }
    if (t < 16 && npairs > 0) {
        int r = t >> 3, k = t & 7;
        sua[0][r][k] = __expf(UA[(size_t)(u0 + r) * KK + k]);
    }
    int par = 0;
    for (int p = 0; p < npairs; ++p, par ^= 1) {
        int u = u0 + 2 * p;
        float e0[8], e1[8], ls0 = 0.f, ls1 = 0.f;
        if (act) {
            e0[0] = __expf(pa0.x); e0[1] = __expf(pa0.y);
            e0[2] = __expf(pa0.z); e0[3] = __expf(pa0.w);
            e0[4] = __expf(pa1.x); e0[5] = __expf(pa1.y);
            e0[6] = __expf(pa1.z); e0[7] = __expf(pa1.w);
            e1[0] = __expf(pb0.x); e1[1] = __expf(pb0.y);
            e1[2] = __expf(pb0.z); e1[3] = __expf(pb0.w);
            e1[4] = __expf(pb1.x); e1[5] = __expf(pb1.y);
            e1[6] = __expf(pb1.z); e1[7] = __expf(pb1.w);
        } else {
#pragma unroll
            for (int j = 0; j < 8; j++) { e0[j] = 0.f; e1[j] = 0.f; }
        }
        if (act && p + 1 < npairs) {  // prefetch next row pair
            const float* r0 = UC + (size_t)(u + 2) * CC + c0;
            pa0 = *(const float4*)r0;        pa1 = *(const float4*)(r0 + 4);
            pb0 = *(const float4*)(r0 + CC); pb1 = *(const float4*)(r0 + CC + 4);
        }
#pragma unroll
        for (int j = 0; j < 8; j++) { ls0 += e0[j]; ls1 += e1[j]; }
#pragma unroll
        for (int o = 16; o; o >>= 1) {
            ls0 += __shfl_xor_sync(0xffffffffu, ls0, o);
            ls1 += __shfl_xor_sync(0xffffffffu, ls1, o);
        }
        if (lane == 0) { red[par][0][wid] = ls0; red[par][1][wid] = ls1; }
        __syncthreads();
        // stage next pair's UA AFTER the barrier (read after the NEXT barrier)
        if (t < 16 && p + 1 < npairs) {
            int r = t >> 3, k = t & 7;
            sua[par ^ 1][r][k] = __expf(UA[(size_t)(u + 2 + r) * KK + k]);
        }
        float s0 = 0.f, s1 = 0.f;
#pragma unroll
        for (int w = 0; w < 8; w++) { s0 += red[par][0][w]; s1 += red[par][1][w]; }
        float inv0 = __fdividef(1.f, s0), inv1 = __fdividef(1.f, s1);
        ull i0p = pack2(inv0, inv0), i1p = pack2(inv1, inv1);
        const ull* sp0 = (const ull*)sua[par][0];
        const ull* sp1 = (const ull*)sua[par][1];
        ull ua0[4], ua1[4];
#pragma unroll
        for (int pp = 0; pp < 4; pp++) {
            ua0[pp] = mul2(sp0[pp], i0p);
            ua1[pp] = mul2(sp1[pp], i1p);
        }
        if (act) {
#pragma unroll
            for (int j = 0; j < 8; j++) {
                ull e0p = pack2(e0[j], e0[j]);
                ull e1p = pack2(e1[j], e1[j]);
#pragma unroll
                for (int pp = 0; pp < 4; pp++) {
                    q[j * 4 + pp] = fma2(e0p, ua0[pp], q[j * 4 + pp]);
                    q[j * 4 + pp] = fma2(e1p, ua1[pp], q[j * 4 + pp]);
                }
            }
        }
    }
    // odd tail row (not hit with current config; kept for safety)
    if (nrows & 1) {
        int u = u1 - 1;
        float e[8], ls = 0.f;
        if (act) {
            const float* r = UC + (size_t)u * CC + c0;
            float4 a = *(const float4*)r, b = *(const float4*)(r + 4);
            e[0] = __expf(a.x); e[1] = __expf(a.y); e[2] = __expf(a.z); e[3] = __expf(a.w);
            e[4] = __expf(b.x); e[5] = __expf(b.y); e[6] = __expf(b.z); e[7] = __expf(b.w);
        } else {
#pragma unroll
            for (int j = 0; j < 8; j++) e[j] = 0.f;
        }
#pragma unroll
        for (int j = 0; j < 8; j++) ls += e[j];
#pragma unroll
        for (int o = 16; o; o >>= 1) ls += __shfl_xor_sync(0xffffffffu, ls, o);
        if (lane == 0) red[par][0][wid] = ls;
        if (t < KK) sua[par][0][t] = __expf(UA[(size_t)u * KK + t]);
        __syncthreads();
        float s = 0.f;
#pragma unroll
        for (int w = 0; w < 8; w++) s += red[par][0][w];
        float inv = __fdividef(1.f, s);
        ull invp = pack2(inv, inv);
        const ull* sp = (const ull*)sua[par][0];
        ull uap[4];
#pragma unroll
        for (int pp = 0; pp < 4; pp++) uap[pp] = mul2(sp[pp], invp);
        if (act) {
#pragma unroll
            for (int j = 0; j < 8; j++) {
                ull ep = pack2(e[j], e[j]);
#pragma unroll
                for (int pp = 0; pp < 4; pp++)
                    q[j * 4 + pp] = fma2(ep, uap[pp], q[j * 4 + pp]);
            }
        }
    }
    if (act) {
        float* dst = g_Qpart + (size_t)blockIdx.x * CK + (size_t)c0 * KK;
#pragma unroll
        for (int j = 0; j < 8; j++) {
            ulonglong2 v0; v0.x = q[j * 4 + 0]; v0.y = q[j * 4 + 1];
            ulonglong2 v1; v1.x = q[j * 4 + 2]; v1.y = q[j * 4 + 3];
            *(ulonglong2*)(dst + j * 8)     = v0;
            *(ulonglong2*)(dst + j * 8 + 4) = v1;
        }
    }
}

// ---- 5: reduce partials (float4) + csum normalization + sigmoid fold ----
__global__ void k_fold(const float* __restrict__ guess_, const float* __restrict__ slide_) {
    __shared__ float sinv[KK];
    if (threadIdx.x < KK) {
        float s = 0.f;
        for (int b = 0; b < UASB; b++) s += g_csum_part[b * KK + threadIdx.x];
        sinv[threadIdx.x] = __fdividef(1.f, s);
    }
    __syncthreads();
    int g4 = blockIdx.x * blockDim.x + threadIdx.x;
    if (g4 >= CK / 4) return;
    int i = g4 * 4;
    float4 s = make_float4(0, 0, 0, 0);
#pragma unroll 4
    for (int b = 0; b < QB; b++) {
        float4 v = *(const float4*)(g_Qpart + (size_t)b * CK + i);
        s.x += v.x; s.y += v.y; s.z += v.z; s.w += v.w;
    }
    int c = i >> 3, k = i & 7;   // k is 0 or 4
    float g  = __fdividef(1.f, 1.f + __expf(-guess_[c]));
    float sl = __fdividef(1.f, 1.f + __expf(-slide_[c]));
    float sc = 1.f - sl - g;
    s.x *= sc * sinv[k];     s.y *= sc * sinv[k + 1];
    s.z *= sc * sinv[k + 2]; s.w *= sc * sinv[k + 3];
    *(float4*)(g_Qs + i) = s;
    if (k == 0) g_gb[c] = g;
}

// ---- 6: Y[i,c] = gb[c] + A[i,:]·Qs[c,:]
//         TWO cols/thread, gridDim.y=4 column split -> q2[8]=16 regs ->
//         ~60 regs total -> 4 blocks/SM (32 warps). 1-ahead row prefetch. ----
__global__ void __launch_bounds__(256, 4) k_y(float* __restrict__ Y, int rpb, int n) {
    int t = threadIdx.x;
    int c0 = blockIdx.y * 512 + t * 2;
    if (c0 >= CC) return;  // no syncs in this kernel; early exit is safe
    ull q2[8], gb2;        // q2[k] = (Qs[c0][k], Qs[c0+1][k])
    {
        const float4* qp = (const float4*)(g_Qs + (size_t)c0 * KK);
        float4 r0 = qp[0], r1 = qp[1];   // row c0
        float4 r2 = qp[2], r3 = qp[3];   // row c0+1
        q2[0] = pack2(r0.x, r2.x); q2[1] = pack2(r0.y, r2.y);
        q2[2] = pack2(r0.z, r2.z); q2[3] = pack2(r0.w, r2.w);
        q2[4] = pack2(r1.x, r3.x); q2[5] = pack2(r1.y, r3.y);
        q2[6] = pack2(r1.z, r3.z); q2[7] = pack2(r1.w, r3.w);
        gb2 = pack2(g_gb[c0], g_gb[c0 + 1]);
    }
    int i0 = blockIdx.x * rpb;
    int i1 = i0 + rpb; if (i1 > n) i1 = n;
    if (i0 >= i1) return;

    // 1-ahead prefetch of the A row (warp-uniform -> LDG broadcast)
    const float4* ap = (const float4*)(g_A + (size_t)i0 * KK);
    float4 n0 = ap[0], n1 = ap[1];
    for (int i = i0; i < i1; ++i) {
        float4 a0 = n0, a1 = n1;
        if (i + 1 < i1) {
            const float4* np = (const float4*)(g_A + (size_t)(i + 1) * KK);
            n0 = np[0]; n1 = np[1];
        }
        ull acc = gb2, apk;
        apk = pack2(a0.x, a0.x); acc = fma2(apk, q2[0], acc);
        apk = pack2(a0.y, a0.y); acc = fma2(apk, q2[1], acc);
        apk = pack2(a0.z, a0.z); acc = fma2(apk, q2[2], acc);
        apk = pack2(a0.w, a0.w); acc = fma2(apk, q2[3], acc);
        apk = pack2(a1.x, a1.x); acc = fma2(apk, q2[4], acc);
        apk = pack2(a1.y, a1.y); acc = fma2(apk, q2[5], acc);
        apk = pack2(a1.z, a1.z); acc = fma2(apk, q2[6], acc);
        apk = pack2(a1.w, a1.w); acc = fma2(apk, q2[7], acc);
        *(ull*)(Y + (size_t)i * CC + c0) = acc;
    }
}

extern "C" void kernel_launch(void* const* d_in, const int* in_sizes, int n_in,
                              void* d_out, int out_size) {
    const float* X      = (const float*)d_in[0];
    const int*   cour   = (const int*)d_in[1];
    const float* CA     = (const float*)d_in[2];
    const float* UA     = (const float*)d_in[3];
    const float* UC     = (const float*)d_in[4];
    const float* guess_ = (const float*)d_in[5];
    const float* slide_ = (const float*)d_in[6];
    float* Y = (float*)d_out;
    int n = in_sizes[1];  // number of samples

    k_ua_sum<<<UASB, 256>>>(UA);
    k_wc<<<CC, 256>>>(CA);
    int warps = (n + 1) / 2;
    k_a<<<(warps + 7) / 8, 256>>>(X, cour, n);
    int rpb = (UU + QB - 1) / QB;
    k_q<<<QB, 256>>>(UC, UA, rpb);
    k_fold<<<(CK / 4 + 255) / 256, 256>>>(guess_, slide_);
    int yrpb = 85;   // 4*ceil(50000/85)=2356 blocks ~= 3.98 waves @ 4 blocks/SM
    dim3 ygrid((n + yrpb - 1) / yrpb, 4);
    k_y<<<ygrid, 256>>>(Y, yrpb, n);
}